// round 2
// baseline (speedup 1.0000x reference)
#include <cuda_runtime.h>
#include <cstdint>
#include <cstddef>

#define NN 4096
#define MM 4096
#define DD 1024
// k = int(4096*4096*0.3) = 5033164 ; ascending 0-based rank = 16777216 - k
#define RANK_ASC 11744052u
#define NB 32          // DP column chunks
#define CW 128         // columns per chunk

// ---------------- static device scratch (no allocations allowed) ----------------
__device__ float    g_z[(size_t)NN * DD];
__device__ float    g_x[(size_t)MM * DD];
__device__ float    g_sim[(size_t)NN * MM];
__device__ unsigned g_diag[(size_t)NN * MM / 32];
__device__ unsigned g_up[(size_t)NN * MM / 32];
__device__ float    g_bound[(size_t)(NN + 1) * NB];
__device__ unsigned g_hist[256];
__device__ unsigned g_sel[2];   // [0]=prefix key, [1]=remaining rank
__device__ float    g_dropline;

// ---------------- helpers ----------------
__device__ __forceinline__ unsigned fkey(float f) {
    unsigned u = __float_as_uint(f);
    return (u & 0x80000000u) ? ~u : (u | 0x80000000u);
}

// ---------------- init (must reset all mutable state every replay) ----------------
__global__ void init_state() {
    int idx = blockIdx.x * blockDim.x + threadIdx.x;
    if (idx < 256) g_hist[idx] = 0u;
    if (idx == 0) { g_sel[0] = 0u; g_sel[1] = RANK_ASC; }
    int total = (NN + 1) * NB;
    for (int i = idx; i < total; i += gridDim.x * blockDim.x)
        g_bound[i] = 1.0f;   // sentinel: real D values are always <= 0
}

__global__ void fill_zero(float* __restrict__ out, size_t n) {
    size_t stride = (size_t)gridDim.x * blockDim.x;
    for (size_t i = blockIdx.x * (size_t)blockDim.x + threadIdx.x; i < n; i += stride)
        out[i] = 0.0f;
}

// ---------------- row normalize ----------------
__global__ void normalize_rows(const float* __restrict__ in, int which) {
    int row = blockIdx.x;
    int t = threadIdx.x;                 // 256 threads
    const float* p = in + (size_t)row * DD;
    float s = 0.f;
#pragma unroll
    for (int k = 0; k < 4; k++) { float v = p[t + k * 256]; s = fmaf(v, v, s); }
    __shared__ float red[256];
    red[t] = s; __syncthreads();
    for (int o = 128; o > 0; o >>= 1) { if (t < o) red[t] += red[t + o]; __syncthreads(); }
    float nrm = sqrtf(red[0]);
    float* q = (which == 0 ? g_z : g_x) + (size_t)row * DD;
#pragma unroll
    for (int k = 0; k < 4; k++) q[t + k * 256] = p[t + k * 256] / nrm;
}

// ---------------- f32 NT GEMM: sim[i][j] = dot(z[i], x[j]), sequential-k accumulation ----------------
__global__ void __launch_bounds__(256) gemm_nt() {
    __shared__ float As[16][132];
    __shared__ float Bs[16][132];
    int tid = threadIdx.x;
    int ty = tid >> 4;   // 0..15
    int tx = tid & 15;   // 0..15
    int bi = blockIdx.y * 128;
    int bj = blockIdx.x * 128;
    float acc[8][8];
#pragma unroll
    for (int r = 0; r < 8; r++)
#pragma unroll
        for (int c = 0; c < 8; c++) acc[r][c] = 0.f;

    for (int k0 = 0; k0 < DD; k0 += 16) {
#pragma unroll
        for (int it = 0; it < 2; ++it) {
            int idx4 = tid + it * 256;       // 0..511
            int arow = idx4 >> 2;            // 0..127
            int a4 = (idx4 & 3) * 4;         // 0,4,8,12
            float4 va = *reinterpret_cast<const float4*>(&g_z[(size_t)(bi + arow) * DD + k0 + a4]);
            As[a4 + 0][arow] = va.x; As[a4 + 1][arow] = va.y;
            As[a4 + 2][arow] = va.z; As[a4 + 3][arow] = va.w;
            float4 vb = *reinterpret_cast<const float4*>(&g_x[(size_t)(bj + arow) * DD + k0 + a4]);
            Bs[a4 + 0][arow] = vb.x; Bs[a4 + 1][arow] = vb.y;
            Bs[a4 + 2][arow] = vb.z; Bs[a4 + 3][arow] = vb.w;
        }
        __syncthreads();
#pragma unroll
        for (int kk = 0; kk < 16; kk++) {
            float a[8], bb[8];
#pragma unroll
            for (int r = 0; r < 8; r++) a[r] = As[kk][ty * 8 + r];
#pragma unroll
            for (int c = 0; c < 8; c++) bb[c] = Bs[kk][tx * 8 + c];
#pragma unroll
            for (int r = 0; r < 8; r++)
#pragma unroll
                for (int c = 0; c < 8; c++)
                    acc[r][c] = fmaf(a[r], bb[c], acc[r][c]);
        }
        __syncthreads();
    }
#pragma unroll
    for (int r = 0; r < 8; r++)
#pragma unroll
        for (int c = 0; c < 8; c++)
            g_sim[(size_t)(bi + ty * 8 + r) * MM + (bj + tx * 8 + c)] = acc[r][c];
}

// ---------------- exact radix select (ascending rank RANK_ASC) ----------------
__global__ void hist_pass(int shift) {
    __shared__ unsigned sh[256];
    if (threadIdx.x < 256) sh[threadIdx.x] = 0u;
    __syncthreads();
    unsigned prefix = g_sel[0];
    int above = shift + 8;
    size_t stride = (size_t)gridDim.x * blockDim.x;
    size_t total = (size_t)NN * MM;
    for (size_t i = blockIdx.x * (size_t)blockDim.x + threadIdx.x; i < total; i += stride) {
        unsigned u = fkey(g_sim[i]);
        bool ok = (above >= 32) || ((u >> above) == (prefix >> above));
        if (ok) atomicAdd(&sh[(u >> shift) & 255u], 1u);
    }
    __syncthreads();
    if (threadIdx.x < 256 && sh[threadIdx.x]) atomicAdd(&g_hist[threadIdx.x], sh[threadIdx.x]);
}

__global__ void select_pass(int shift, int last) {
    __shared__ unsigned cnt[256];
    int t = threadIdx.x;
    cnt[t] = g_hist[t];
    g_hist[t] = 0u;   // reset for the next pass
    __syncthreads();
    if (t == 0) {
        unsigned rank = g_sel[1], cum = 0; int bin = 255;
        for (int b = 0; b < 256; b++) {
            unsigned c = cnt[b];
            if (cum + c > rank) { bin = b; break; }
            cum += c;
        }
        g_sel[0] |= ((unsigned)bin) << shift;
        g_sel[1] = rank - cum;
        if (last) {
            unsigned u = g_sel[0];
            unsigned bits = (u & 0x80000000u) ? (u & 0x7FFFFFFFu) : ~u;
            g_dropline = __uint_as_float(bits);
        }
    }
}

// ---------------- NW DP wavefront (32-block pipeline, value-as-flag handoff) ----------------
__device__ __forceinline__ float poll_bound(int i, int b) {
    volatile float* p = (volatile float*)&g_bound[(size_t)i * NB + b];
    float v = *p;
    while (v > 0.5f) v = *p;   // real D values are <= 0
    return v;
}

__global__ void __launch_bounds__(128, 1) dp_kernel() {
    const int b = blockIdx.x;
    const int t = threadIdx.x, warp = t >> 5, lane = t & 31;
    const int c0 = b * CW;
    __shared__ float s_agg[2][4];
    __shared__ float s_edge[2][4];
    if (t < 4) { s_edge[0][t] = 0.f; s_edge[1][t] = 0.f; }
    __syncthreads();
    const float dropline = g_dropline;
    float myPrev = 0.f;        // D[i-1][c0 + t + 1]
    float prevBound = 0.f;     // D[i-1][c0]
    float simCur = g_sim[(size_t)0 * MM + c0 + t];   // C row for DP row i uses sim row i-1

    for (int i = 1; i <= NN; ++i) {
        int par = i & 1;
        float simNext = (i < NN) ? g_sim[(size_t)i * MM + c0 + t] : 0.f;   // prefetch
        float c = dropline - simCur;
        float leftPrev = __shfl_up_sync(0xffffffffu, myPrev, 1);
        if (lane == 0) leftPrev = (warp == 0) ? prevBound : s_edge[par ^ 1][warp - 1];
        float diagCand = leftPrev + c;               // D[i-1][j-1] + C[i-1][j-1]
        float cand = fminf(diagCand, myPrev);        // min(diag, up)
        // inclusive warp min-scan
        float s = cand;
#pragma unroll
        for (int o = 1; o < 32; o <<= 1) {
            float v = __shfl_up_sync(0xffffffffu, s, o);
            if (lane >= o) s = fminf(s, v);
        }
        if (lane == 31) s_agg[par][warp] = s;
        __syncthreads();
        float incoming = (b == 0) ? 0.f : poll_bound(i, b);   // D[i][c0] (prefix-min seed)
        float seed = incoming;
#pragma unroll
        for (int w = 0; w < 3; ++w)
            if (w < warp) seed = fminf(seed, s_agg[par][w]);
        float newD = fminf(seed, s);                  // D[i][c0 + t + 1]
        bool dflag = (newD == diagCand);
        bool uflag = (!dflag) && (newD == myPrev);
        unsigned db = __ballot_sync(0xffffffffu, dflag);
        unsigned ub = __ballot_sync(0xffffffffu, uflag);
        if (lane == 0) {
            size_t widx = (size_t)(i - 1) * (MM / 32) + (c0 >> 5) + warp;
            g_diag[widx] = db;
            g_up[widx] = ub;
        }
        myPrev = newD;
        prevBound = incoming;
        if (lane == 31) s_edge[par][warp] = newD;
        if (t == CW - 1 && b < NB - 1) {
            volatile float* p = (volatile float*)&g_bound[(size_t)i * NB + (b + 1)];
            *p = newD;   // publish D[i][c0 + CW] to the right neighbor
        }
        simCur = simNext;
        __syncthreads();
    }
}

// ---------------- traceback (shared-tile staged walk) ----------------
__global__ void traceback(float* __restrict__ out) {
    __shared__ unsigned s_d[64 * 4], s_u[64 * 4];
    __shared__ int s_ij[2];
    int t = threadIdx.x;    // 128 threads
    int i = NN, j = MM;
    while (i > 0 && j > 0) {
        int ilo = (i - 63 > 1) ? (i - 63) : 1;
        int whi = (j - 1) >> 5;
        int wlo = (whi - 3 > 0) ? (whi - 3) : 0;
        int rows = i - ilo + 1;
        for (int idx = t; idx < rows * 4; idx += 128) {
            int r = idx >> 2, w = idx & 3;
            size_t g = (size_t)(ilo - 1 + r) * (MM / 32) + wlo + w;
            s_d[r * 4 + w] = g_diag[g];
            s_u[r * 4 + w] = g_up[g];
        }
        __syncthreads();
        if (t == 0) {
            int jlo = wlo * 32 + 1;
            while (i >= ilo && j >= jlo) {
                int r = i - ilo;
                int w = ((j - 1) >> 5) - wlo;
                int bit = (j - 1) & 31;
                unsigned dd = (s_d[r * 4 + w] >> bit) & 1u;
                if (dd) { out[(size_t)(i - 1) * MM + (j - 1)] = 1.0f; --i; --j; }
                else if ((s_u[r * 4 + w] >> bit) & 1u) { --i; }
                else { --j; }
            }
            s_ij[0] = i; s_ij[1] = j;
        }
        __syncthreads();
        i = s_ij[0]; j = s_ij[1];
        __syncthreads();
        // i==0 or j==0 => only zero-cost up/left moves remain, no more writes
    }
}

// ---------------- launch ----------------
extern "C" void kernel_launch(void* const* d_in, const int* in_sizes, int n_in,
                              void* d_out, int out_size) {
    (void)in_sizes; (void)n_in; (void)out_size;
    const float* text  = (const float*)d_in[2];
    const float* event = (const float*)d_in[3];
    float* out = (float*)d_out;

    init_state<<<256, 256>>>();
    fill_zero<<<4096, 256>>>(out, (size_t)NN * MM);
    normalize_rows<<<NN, 256>>>(text, 0);
    normalize_rows<<<MM, 256>>>(event, 1);
    gemm_nt<<<dim3(32, 32), 256>>>();
    for (int p = 0; p < 4; ++p) {
        int shift = 24 - 8 * p;
        hist_pass<<<2048, 256>>>(shift);
        select_pass<<<1, 256>>>(shift, p == 3 ? 1 : 0);
    }
    dp_kernel<<<NB, CW>>>();
    traceback<<<1, 128>>>(out);
}

// round 3
// speedup vs baseline: 1.0346x; 1.0346x over previous
#include <cuda_runtime.h>
#include <cstdint>
#include <cstddef>

#define NN 4096
#define MM 4096
#define DD 1024
// k = int(4096*4096*0.3) = 5033164 ; ascending 0-based rank = 16777216 - k
#define RANK_ASC 11744052u
#define NB 32          // DP column chunks
#define CW 128         // columns per chunk

// ---------------- static device scratch (no allocations allowed) ----------------
__device__ float    g_z[(size_t)NN * DD];
__device__ float    g_x[(size_t)MM * DD];
__device__ float    g_sim[(size_t)NN * MM];
__device__ unsigned g_diag[(size_t)NN * MM / 32];
__device__ unsigned g_up[(size_t)NN * MM / 32];
__device__ float    g_bound[(size_t)(NN + 1) * NB];
__device__ unsigned g_hist[256];
__device__ unsigned g_sel[2];   // [0]=prefix key, [1]=remaining rank
__device__ float    g_dropline;

// ---------------- helpers ----------------
__device__ __forceinline__ unsigned fkey(float f) {
    unsigned u = __float_as_uint(f);
    return (u & 0x80000000u) ? ~u : (u | 0x80000000u);
}

// ---------------- init (must reset all mutable state every replay) ----------------
__global__ void init_state() {
    int idx = blockIdx.x * blockDim.x + threadIdx.x;
    if (idx < 256) g_hist[idx] = 0u;
    if (idx == 0) { g_sel[0] = 0u; g_sel[1] = RANK_ASC; }
    int total = (NN + 1) * NB;
    for (int i = idx; i < total; i += gridDim.x * blockDim.x)
        g_bound[i] = 1.0f;   // sentinel: real D values are always <= 0
}

__global__ void fill_zero(float* __restrict__ out, size_t n) {
    size_t stride = (size_t)gridDim.x * blockDim.x;
    for (size_t i = blockIdx.x * (size_t)blockDim.x + threadIdx.x; i < n; i += stride)
        out[i] = 0.0f;
}

// ---------------- row normalize ----------------
__global__ void normalize_rows(const float* __restrict__ in, int which) {
    int row = blockIdx.x;
    int t = threadIdx.x;                 // 256 threads
    const float* p = in + (size_t)row * DD;
    float s = 0.f;
#pragma unroll
    for (int k = 0; k < 4; k++) { float v = p[t + k * 256]; s = fmaf(v, v, s); }
    __shared__ float red[256];
    red[t] = s; __syncthreads();
    for (int o = 128; o > 0; o >>= 1) { if (t < o) red[t] += red[t + o]; __syncthreads(); }
    float nrm = sqrtf(red[0]);
    float* q = (which == 0 ? g_z : g_x) + (size_t)row * DD;
#pragma unroll
    for (int k = 0; k < 4; k++) q[t + k * 256] = p[t + k * 256] / nrm;
}

// ---------------- f32 NT GEMM, double-buffered smem, sequential-k accumulation ----------------
__global__ void __launch_bounds__(256) gemm_nt() {
    __shared__ float As[2][16][132];
    __shared__ float Bs[2][16][132];
    int tid = threadIdx.x;
    int ty = tid >> 4;   // 0..15
    int tx = tid & 15;   // 0..15
    int bi = blockIdx.y * 128;
    int bj = blockIdx.x * 128;

    // loader mapping: thread loads rows arow0 and arow0+64, 4 floats at col a4
    int arow0 = tid >> 2;            // 0..63
    int a4 = (tid & 3) * 4;          // 0,4,8,12

    float acc[8][8];
#pragma unroll
    for (int r = 0; r < 8; r++)
#pragma unroll
        for (int c = 0; c < 8; c++) acc[r][c] = 0.f;

    // preload chunk 0 into buffer 0
    {
        float4 va0 = *reinterpret_cast<const float4*>(&g_z[(size_t)(bi + arow0) * DD + a4]);
        float4 va1 = *reinterpret_cast<const float4*>(&g_z[(size_t)(bi + arow0 + 64) * DD + a4]);
        float4 vb0 = *reinterpret_cast<const float4*>(&g_x[(size_t)(bj + arow0) * DD + a4]);
        float4 vb1 = *reinterpret_cast<const float4*>(&g_x[(size_t)(bj + arow0 + 64) * DD + a4]);
        As[0][a4 + 0][arow0] = va0.x; As[0][a4 + 1][arow0] = va0.y;
        As[0][a4 + 2][arow0] = va0.z; As[0][a4 + 3][arow0] = va0.w;
        As[0][a4 + 0][arow0 + 64] = va1.x; As[0][a4 + 1][arow0 + 64] = va1.y;
        As[0][a4 + 2][arow0 + 64] = va1.z; As[0][a4 + 3][arow0 + 64] = va1.w;
        Bs[0][a4 + 0][arow0] = vb0.x; Bs[0][a4 + 1][arow0] = vb0.y;
        Bs[0][a4 + 2][arow0] = vb0.z; Bs[0][a4 + 3][arow0] = vb0.w;
        Bs[0][a4 + 0][arow0 + 64] = vb1.x; Bs[0][a4 + 1][arow0 + 64] = vb1.y;
        Bs[0][a4 + 2][arow0 + 64] = vb1.z; Bs[0][a4 + 3][arow0 + 64] = vb1.w;
    }
    __syncthreads();

    int s = 0;
    for (int k0 = 0; k0 < DD; k0 += 16, s ^= 1) {
        float4 va0, va1, vb0, vb1;
        bool more = (k0 + 16 < DD);
        if (more) {
            int kn = k0 + 16;
            va0 = *reinterpret_cast<const float4*>(&g_z[(size_t)(bi + arow0) * DD + kn + a4]);
            va1 = *reinterpret_cast<const float4*>(&g_z[(size_t)(bi + arow0 + 64) * DD + kn + a4]);
            vb0 = *reinterpret_cast<const float4*>(&g_x[(size_t)(bj + arow0) * DD + kn + a4]);
            vb1 = *reinterpret_cast<const float4*>(&g_x[(size_t)(bj + arow0 + 64) * DD + kn + a4]);
        }
#pragma unroll
        for (int kk = 0; kk < 16; kk++) {
            float a[8], bb[8];
            const float4* ap = reinterpret_cast<const float4*>(&As[s][kk][ty * 8]);
            const float4* bp = reinterpret_cast<const float4*>(&Bs[s][kk][tx * 8]);
            float4 a0 = ap[0], a1 = ap[1];
            float4 b0 = bp[0], b1 = bp[1];
            a[0] = a0.x; a[1] = a0.y; a[2] = a0.z; a[3] = a0.w;
            a[4] = a1.x; a[5] = a1.y; a[6] = a1.z; a[7] = a1.w;
            bb[0] = b0.x; bb[1] = b0.y; bb[2] = b0.z; bb[3] = b0.w;
            bb[4] = b1.x; bb[5] = b1.y; bb[6] = b1.z; bb[7] = b1.w;
#pragma unroll
            for (int r = 0; r < 8; r++)
#pragma unroll
                for (int c = 0; c < 8; c++)
                    acc[r][c] = fmaf(a[r], bb[c], acc[r][c]);
        }
        __syncthreads();
        if (more) {
            int d = s ^ 1;
            As[d][a4 + 0][arow0] = va0.x; As[d][a4 + 1][arow0] = va0.y;
            As[d][a4 + 2][arow0] = va0.z; As[d][a4 + 3][arow0] = va0.w;
            As[d][a4 + 0][arow0 + 64] = va1.x; As[d][a4 + 1][arow0 + 64] = va1.y;
            As[d][a4 + 2][arow0 + 64] = va1.z; As[d][a4 + 3][arow0 + 64] = va1.w;
            Bs[d][a4 + 0][arow0] = vb0.x; Bs[d][a4 + 1][arow0] = vb0.y;
            Bs[d][a4 + 2][arow0] = vb0.z; Bs[d][a4 + 3][arow0] = vb0.w;
            Bs[d][a4 + 0][arow0 + 64] = vb1.x; Bs[d][a4 + 1][arow0 + 64] = vb1.y;
            Bs[d][a4 + 2][arow0 + 64] = vb1.z; Bs[d][a4 + 3][arow0 + 64] = vb1.w;
            __syncthreads();
        }
    }
#pragma unroll
    for (int r = 0; r < 8; r++) {
        float4 o0, o1;
        o0.x = acc[r][0]; o0.y = acc[r][1]; o0.z = acc[r][2]; o0.w = acc[r][3];
        o1.x = acc[r][4]; o1.y = acc[r][5]; o1.z = acc[r][6]; o1.w = acc[r][7];
        float* dst = &g_sim[(size_t)(bi + ty * 8 + r) * MM + (bj + tx * 8)];
        *reinterpret_cast<float4*>(dst) = o0;
        *reinterpret_cast<float4*>(dst + 4) = o1;
    }
}

// ---------------- exact radix select (ascending rank RANK_ASC) ----------------
__global__ void hist_pass(int shift) {
    __shared__ unsigned sh[256];
    if (threadIdx.x < 256) sh[threadIdx.x] = 0u;
    __syncthreads();
    unsigned prefix = g_sel[0];
    int above = shift + 8;
    size_t stride = (size_t)gridDim.x * blockDim.x;
    size_t total = (size_t)NN * MM;
    for (size_t i = blockIdx.x * (size_t)blockDim.x + threadIdx.x; i < total; i += stride) {
        unsigned u = fkey(g_sim[i]);
        bool ok = (above >= 32) || ((u >> above) == (prefix >> above));
        if (ok) atomicAdd(&sh[(u >> shift) & 255u], 1u);
    }
    __syncthreads();
    if (threadIdx.x < 256 && sh[threadIdx.x]) atomicAdd(&g_hist[threadIdx.x], sh[threadIdx.x]);
}

__global__ void select_pass(int shift, int last) {
    __shared__ unsigned cnt[256];
    int t = threadIdx.x;
    cnt[t] = g_hist[t];
    g_hist[t] = 0u;   // reset for the next pass
    __syncthreads();
    if (t == 0) {
        unsigned rank = g_sel[1], cum = 0; int bin = 255;
        for (int b = 0; b < 256; b++) {
            unsigned c = cnt[b];
            if (cum + c > rank) { bin = b; break; }
            cum += c;
        }
        g_sel[0] |= ((unsigned)bin) << shift;
        g_sel[1] = rank - cum;
        if (last) {
            unsigned u = g_sel[0];
            unsigned bits = (u & 0x80000000u) ? (u & 0x7FFFFFFFu) : ~u;
            g_dropline = __uint_as_float(bits);
        }
    }
}

// ---------------- NW DP wavefront: single-warp blocks, 4 cols/lane, no barriers ----------------
// Bit layout: 0-based sim column jj -> word (jj>>7)*4 + (jj&3), bit (jj>>2)&31.
__global__ void __launch_bounds__(32, 1) dp_kernel() {
    const int b = blockIdx.x;
    const int lane = threadIdx.x;          // 32 lanes, lane handles cols c0+4*lane .. +3
    const int c0 = b * CW;
    const float dropline = g_dropline;

    float prev0 = 0.f, prev1 = 0.f, prev2 = 0.f, prev3 = 0.f;  // D[i-1] at this lane's 4 cols
    float prevBound = 0.f;                                      // D[i-1][c0]
    const float* simBase = g_sim + c0 + 4 * lane;
    float4 simCur = *reinterpret_cast<const float4*>(simBase);  // sim row 0

    for (int i = 1; i <= NN; ++i) {
        float4 simNext;
        if (i < NN) simNext = *reinterpret_cast<const float4*>(simBase + (size_t)i * MM);
        else { simNext.x = simNext.y = simNext.z = simNext.w = 0.f; }

        volatile float* pb = (volatile float*)&g_bound[(size_t)i * NB + b];
        float incoming = (b == 0) ? 0.f : *pb;   // issue early; verify later

        float cc0 = dropline - simCur.x;
        float cc1 = dropline - simCur.y;
        float cc2 = dropline - simCur.z;
        float cc3 = dropline - simCur.w;

        float edge = __shfl_up_sync(0xffffffffu, prev3, 1);   // D[i-1][c0+4*lane]
        float left0 = (lane == 0) ? prevBound : edge;

        float d0 = left0 + cc0;
        float d1 = prev0 + cc1;
        float d2 = prev1 + cc2;
        float d3 = prev2 + cc3;
        float n0 = fminf(d0, prev0);
        float n1 = fminf(d1, prev1);
        float n2 = fminf(d2, prev2);
        float n3 = fminf(d3, prev3);
        float p0 = n0;
        float p1 = fminf(p0, n1);
        float p2 = fminf(p1, n2);
        float p3 = fminf(p2, n3);

        // warp inclusive min-scan of lane totals
        float S = p3;
#pragma unroll
        for (int o = 1; o < 32; o <<= 1) {
            float v = __shfl_up_sync(0xffffffffu, S, o);
            if (lane >= o) S = fminf(S, v);
        }
        float E = __shfl_up_sync(0xffffffffu, S, 1);   // exclusive prefix (lanes > 0)

        if (b != 0) { while (incoming > 0.5f) incoming = *pb; }

        float base = (lane == 0) ? incoming : fminf(incoming, E);
        float D0 = fminf(base, p0);
        float D1 = fminf(base, p1);
        float D2 = fminf(base, p2);
        float D3 = fminf(base, p3);

        // publish right boundary ASAP (lane 31's D3 == min(incoming, S_31))
        if (lane == 31 && b < NB - 1) {
            volatile float* q = (volatile float*)&g_bound[(size_t)i * NB + (b + 1)];
            *q = D3;
        }

        bool df0 = (D0 == d0); bool uf0 = (!df0) && (D0 == prev0);
        bool df1 = (D1 == d1); bool uf1 = (!df1) && (D1 == prev1);
        bool df2 = (D2 == d2); bool uf2 = (!df2) && (D2 == prev2);
        bool df3 = (D3 == d3); bool uf3 = (!df3) && (D3 == prev3);
        unsigned db0 = __ballot_sync(0xffffffffu, df0);
        unsigned db1 = __ballot_sync(0xffffffffu, df1);
        unsigned db2 = __ballot_sync(0xffffffffu, df2);
        unsigned db3 = __ballot_sync(0xffffffffu, df3);
        unsigned ub0 = __ballot_sync(0xffffffffu, uf0);
        unsigned ub1 = __ballot_sync(0xffffffffu, uf1);
        unsigned ub2 = __ballot_sync(0xffffffffu, uf2);
        unsigned ub3 = __ballot_sync(0xffffffffu, uf3);
        if (lane < 4) {
            unsigned vd = (lane == 0) ? db0 : (lane == 1) ? db1 : (lane == 2) ? db2 : db3;
            unsigned vu = (lane == 0) ? ub0 : (lane == 1) ? ub1 : (lane == 2) ? ub2 : ub3;
            size_t rowbase = (size_t)(i - 1) * (MM / 32) + b * 4;
            g_diag[rowbase + lane] = vd;
            g_up[rowbase + lane] = vu;
        }

        prev0 = D0; prev1 = D1; prev2 = D2; prev3 = D3;
        prevBound = incoming;
        simCur = simNext;
    }
}

// ---------------- traceback (128-row x 256-col shared tiles) ----------------
// Decision-bit query for 0-based col jj: word (jj>>7)*4 + (jj&3), bit (jj>>2)&31.
__global__ void traceback(float* __restrict__ out) {
    __shared__ unsigned s_d[128 * 8], s_u[128 * 8];
    __shared__ int s_ij[2];
    int t = threadIdx.x;    // 256 threads
    int i = NN, j = MM;
    while (i > 0 && j > 0) {
        int ilo = (i - 127 > 1) ? (i - 127) : 1;
        int jbhi = (j - 1) >> 7;                       // block-col of current jj
        int jblo = (jbhi - 1 > 0) ? (jbhi - 1) : 0;    // stage 2 block-cols
        int rows = i - ilo + 1;
        for (int idx = t; idx < rows * 8; idx += 256) {
            int r = idx >> 3, w = idx & 7;
            size_t g = (size_t)(ilo - 1 + r) * (MM / 32) + jblo * 4 + w;
            s_d[r * 8 + w] = g_diag[g];
            s_u[r * 8 + w] = g_up[g];
        }
        __syncthreads();
        if (t == 0) {
            int jlo = jblo * 128 + 1;
            while (i >= ilo && j >= jlo) {
                int jj = j - 1;
                int r = i - ilo;
                int w = ((jj >> 7) - jblo) * 4 + (jj & 3);
                int bit = (jj >> 2) & 31;
                if ((s_d[r * 8 + w] >> bit) & 1u) {
                    out[(size_t)(i - 1) * MM + jj] = 1.0f; --i; --j;
                } else if ((s_u[r * 8 + w] >> bit) & 1u) {
                    --i;
                } else {
                    --j;
                }
            }
            s_ij[0] = i; s_ij[1] = j;
        }
        __syncthreads();
        i = s_ij[0]; j = s_ij[1];
        __syncthreads();
        // i==0 or j==0 => only zero-cost up/left moves remain, no more writes
    }
}

// ---------------- launch ----------------
extern "C" void kernel_launch(void* const* d_in, const int* in_sizes, int n_in,
                              void* d_out, int out_size) {
    (void)in_sizes; (void)n_in; (void)out_size;
    const float* text  = (const float*)d_in[2];
    const float* event = (const float*)d_in[3];
    float* out = (float*)d_out;

    init_state<<<256, 256>>>();
    fill_zero<<<4096, 256>>>(out, (size_t)NN * MM);
    normalize_rows<<<NN, 256>>>(text, 0);
    normalize_rows<<<MM, 256>>>(event, 1);
    gemm_nt<<<dim3(32, 32), 256>>>();
    for (int p = 0; p < 4; ++p) {
        int shift = 24 - 8 * p;
        hist_pass<<<2048, 256>>>(shift);
        select_pass<<<1, 256>>>(shift, p == 3 ? 1 : 0);
    }
    dp_kernel<<<NB, 32>>>();
    traceback<<<1, 256>>>(out);
}

// round 5
// speedup vs baseline: 1.0450x; 1.0101x over previous
#include <cuda_runtime.h>
#include <cstdint>
#include <cstddef>

#define NN 4096
#define MM 4096
#define DD 1024
// k = int(4096*4096*0.3) = 5033164 ; ascending 0-based rank = 16777216 - k
#define RANK_ASC 11744052u
#define NB 32          // DP column chunks
#define CW 128         // columns per chunk
#define PF 8           // sim prefetch ring depth (power of 2)

// ---------------- static device scratch (no allocations allowed) ----------------
__device__ float    g_z[(size_t)NN * DD];
__device__ float    g_x[(size_t)MM * DD];
__device__ float    g_sim[(size_t)NN * MM];
__device__ unsigned g_diag[(size_t)NN * MM / 32];
__device__ unsigned g_up[(size_t)NN * MM / 32];
__device__ float    g_bound[(size_t)(NN + 1) * NB];
__device__ unsigned g_hist[256];
__device__ unsigned g_sel[2];   // [0]=prefix key, [1]=remaining rank
__device__ float    g_dropline;

// ---------------- helpers ----------------
__device__ __forceinline__ unsigned fkey(float f) {
    unsigned u = __float_as_uint(f);
    return (u & 0x80000000u) ? ~u : (u | 0x80000000u);
}

// ---------------- init (must reset all mutable state every replay) ----------------
__global__ void init_state() {
    int idx = blockIdx.x * blockDim.x + threadIdx.x;
    if (idx < 256) g_hist[idx] = 0u;
    if (idx == 0) { g_sel[0] = 0u; g_sel[1] = RANK_ASC; }
    int total = (NN + 1) * NB;
    for (int i = idx; i < total; i += gridDim.x * blockDim.x)
        g_bound[i] = 1.0f;   // sentinel: real D values are always <= 0
}

__global__ void fill_zero(float* __restrict__ out, size_t n) {
    size_t stride = (size_t)gridDim.x * blockDim.x;
    for (size_t i = blockIdx.x * (size_t)blockDim.x + threadIdx.x; i < n; i += stride)
        out[i] = 0.0f;
}

// ---------------- row normalize ----------------
__global__ void normalize_rows(const float* __restrict__ in, int which) {
    int row = blockIdx.x;
    int t = threadIdx.x;                 // 256 threads
    const float* p = in + (size_t)row * DD;
    float s = 0.f;
#pragma unroll
    for (int k = 0; k < 4; k++) { float v = p[t + k * 256]; s = fmaf(v, v, s); }
    __shared__ float red[256];
    red[t] = s; __syncthreads();
    for (int o = 128; o > 0; o >>= 1) { if (t < o) red[t] += red[t + o]; __syncthreads(); }
    float nrm = sqrtf(red[0]);
    float* q = (which == 0 ? g_z : g_x) + (size_t)row * DD;
#pragma unroll
    for (int k = 0; k < 4; k++) q[t + k * 256] = p[t + k * 256] / nrm;
}

// ---------------- f32 NT GEMM, double-buffered smem, f32x2 packed FMA ----------------
// Accumulation order identical to scalar version (same k sequence, per-component
// IEEE fma) => bitwise-identical sim.
__global__ void __launch_bounds__(256) gemm_nt() {
    __shared__ __align__(16) float As[2][16][132];
    __shared__ __align__(16) float Bs[2][16][132];
    int tid = threadIdx.x;
    int ty = tid >> 4;   // 0..15
    int tx = tid & 15;   // 0..15
    int bi = blockIdx.y * 128;
    int bj = blockIdx.x * 128;

    int arow0 = tid >> 2;            // 0..63
    int a4 = (tid & 3) * 4;          // 0,4,8,12

    // acc2[rp][c] packs rows (ty*8+2rp, ty*8+2rp+1) at column tx*8+c
    unsigned long long acc2[4][8];
#pragma unroll
    for (int rp = 0; rp < 4; rp++)
#pragma unroll
        for (int c = 0; c < 8; c++) acc2[rp][c] = 0ull;

    {
        float4 va0 = *reinterpret_cast<const float4*>(&g_z[(size_t)(bi + arow0) * DD + a4]);
        float4 va1 = *reinterpret_cast<const float4*>(&g_z[(size_t)(bi + arow0 + 64) * DD + a4]);
        float4 vb0 = *reinterpret_cast<const float4*>(&g_x[(size_t)(bj + arow0) * DD + a4]);
        float4 vb1 = *reinterpret_cast<const float4*>(&g_x[(size_t)(bj + arow0 + 64) * DD + a4]);
        As[0][a4 + 0][arow0] = va0.x; As[0][a4 + 1][arow0] = va0.y;
        As[0][a4 + 2][arow0] = va0.z; As[0][a4 + 3][arow0] = va0.w;
        As[0][a4 + 0][arow0 + 64] = va1.x; As[0][a4 + 1][arow0 + 64] = va1.y;
        As[0][a4 + 2][arow0 + 64] = va1.z; As[0][a4 + 3][arow0 + 64] = va1.w;
        Bs[0][a4 + 0][arow0] = vb0.x; Bs[0][a4 + 1][arow0] = vb0.y;
        Bs[0][a4 + 2][arow0] = vb0.z; Bs[0][a4 + 3][arow0] = vb0.w;
        Bs[0][a4 + 0][arow0 + 64] = vb1.x; Bs[0][a4 + 1][arow0 + 64] = vb1.y;
        Bs[0][a4 + 2][arow0 + 64] = vb1.z; Bs[0][a4 + 3][arow0 + 64] = vb1.w;
    }
    __syncthreads();

    int s = 0;
    for (int k0 = 0; k0 < DD; k0 += 16, s ^= 1) {
        float4 va0, va1, vb0, vb1;
        bool more = (k0 + 16 < DD);
        if (more) {
            int kn = k0 + 16;
            va0 = *reinterpret_cast<const float4*>(&g_z[(size_t)(bi + arow0) * DD + kn + a4]);
            va1 = *reinterpret_cast<const float4*>(&g_z[(size_t)(bi + arow0 + 64) * DD + kn + a4]);
            vb0 = *reinterpret_cast<const float4*>(&g_x[(size_t)(bj + arow0) * DD + kn + a4]);
            vb1 = *reinterpret_cast<const float4*>(&g_x[(size_t)(bj + arow0 + 64) * DD + kn + a4]);
        }
#pragma unroll
        for (int kk = 0; kk < 16; kk++) {
            const ulonglong2* ap2 = reinterpret_cast<const ulonglong2*>(&As[s][kk][ty * 8]);
            ulonglong2 aa = ap2[0], ab = ap2[1];
            unsigned long long a2[4];
            a2[0] = aa.x; a2[1] = aa.y; a2[2] = ab.x; a2[3] = ab.y;
            const float4* bp = reinterpret_cast<const float4*>(&Bs[s][kk][tx * 8]);
            float4 b0 = bp[0], b1 = bp[1];
            float bbv[8];
            bbv[0] = b0.x; bbv[1] = b0.y; bbv[2] = b0.z; bbv[3] = b0.w;
            bbv[4] = b1.x; bbv[5] = b1.y; bbv[6] = b1.z; bbv[7] = b1.w;
            unsigned long long b2[8];
#pragma unroll
            for (int c = 0; c < 8; c++)
                asm("mov.b64 %0, {%1, %1};" : "=l"(b2[c]) : "r"(__float_as_uint(bbv[c])));
#pragma unroll
            for (int rp = 0; rp < 4; rp++)
#pragma unroll
                for (int c = 0; c < 8; c++)
                    asm("fma.rn.f32x2 %0, %1, %2, %0;"
                        : "+l"(acc2[rp][c]) : "l"(a2[rp]), "l"(b2[c]));
        }
        __syncthreads();
        if (more) {
            int d = s ^ 1;
            As[d][a4 + 0][arow0] = va0.x; As[d][a4 + 1][arow0] = va0.y;
            As[d][a4 + 2][arow0] = va0.z; As[d][a4 + 3][arow0] = va0.w;
            As[d][a4 + 0][arow0 + 64] = va1.x; As[d][a4 + 1][arow0 + 64] = va1.y;
            As[d][a4 + 2][arow0 + 64] = va1.z; As[d][a4 + 3][arow0 + 64] = va1.w;
            Bs[d][a4 + 0][arow0] = vb0.x; Bs[d][a4 + 1][arow0] = vb0.y;
            Bs[d][a4 + 2][arow0] = vb0.z; Bs[d][a4 + 3][arow0] = vb0.w;
            Bs[d][a4 + 0][arow0 + 64] = vb1.x; Bs[d][a4 + 1][arow0 + 64] = vb1.y;
            Bs[d][a4 + 2][arow0 + 64] = vb1.z; Bs[d][a4 + 3][arow0 + 64] = vb1.w;
            __syncthreads();
        }
    }
#pragma unroll
    for (int rp = 0; rp < 4; rp++) {
        float lo[8], hi[8];
#pragma unroll
        for (int c = 0; c < 8; c++) {
            lo[c] = __uint_as_float((unsigned)(acc2[rp][c] & 0xffffffffull));
            hi[c] = __uint_as_float((unsigned)(acc2[rp][c] >> 32));
        }
        float* dst0 = &g_sim[(size_t)(bi + ty * 8 + 2 * rp) * MM + (bj + tx * 8)];
        float* dst1 = &g_sim[(size_t)(bi + ty * 8 + 2 * rp + 1) * MM + (bj + tx * 8)];
        float4 o;
        o.x = lo[0]; o.y = lo[1]; o.z = lo[2]; o.w = lo[3];
        *reinterpret_cast<float4*>(dst0) = o;
        o.x = lo[4]; o.y = lo[5]; o.z = lo[6]; o.w = lo[7];
        *reinterpret_cast<float4*>(dst0 + 4) = o;
        o.x = hi[0]; o.y = hi[1]; o.z = hi[2]; o.w = hi[3];
        *reinterpret_cast<float4*>(dst1) = o;
        o.x = hi[4]; o.y = hi[5]; o.z = hi[6]; o.w = hi[7];
        *reinterpret_cast<float4*>(dst1 + 4) = o;
    }
}

// ---------------- exact radix select (ascending rank RANK_ASC) ----------------
__global__ void hist_pass(int shift) {
    __shared__ unsigned sh[256];
    if (threadIdx.x < 256) sh[threadIdx.x] = 0u;
    __syncthreads();
    unsigned prefix = g_sel[0];
    int above = shift + 8;
    size_t stride = (size_t)gridDim.x * blockDim.x;
    size_t total = (size_t)NN * MM;
    for (size_t i = blockIdx.x * (size_t)blockDim.x + threadIdx.x; i < total; i += stride) {
        unsigned u = fkey(g_sim[i]);
        bool ok = (above >= 32) || ((u >> above) == (prefix >> above));
        if (ok) atomicAdd(&sh[(u >> shift) & 255u], 1u);
    }
    __syncthreads();
    if (threadIdx.x < 256 && sh[threadIdx.x]) atomicAdd(&g_hist[threadIdx.x], sh[threadIdx.x]);
}

__global__ void select_pass(int shift, int last) {
    __shared__ unsigned cnt[256];
    int t = threadIdx.x;
    cnt[t] = g_hist[t];
    g_hist[t] = 0u;   // reset for the next pass
    __syncthreads();
    if (t == 0) {
        unsigned rank = g_sel[1], cum = 0; int bin = 255;
        for (int b = 0; b < 256; b++) {
            unsigned c = cnt[b];
            if (cum + c > rank) { bin = b; break; }
            cum += c;
        }
        g_sel[0] |= ((unsigned)bin) << shift;
        g_sel[1] = rank - cum;
        if (last) {
            unsigned u = g_sel[0];
            unsigned bits = (u & 0x80000000u) ? (u & 0x7FFFFFFFu) : ~u;
            g_dropline = __uint_as_float(bits);
        }
    }
}

// ---------------- NW DP wavefront: single-warp blocks, per-row volatile handoff,
// ---------------- cp.async depth-8 sim prefetch ring ----------------
// Bit layout: 0-based sim column jj -> word (jj>>7)*4 + (jj&3), bit (jj>>2)&31.
__global__ void __launch_bounds__(32, 1) dp_kernel() {
    const int b = blockIdx.x;
    const int lane = threadIdx.x;          // 32 lanes, lane handles cols c0+4*lane .. +3
    const int c0 = b * CW;
    const float dropline = g_dropline;

    __shared__ __align__(16) float s_sim[PF][CW];   // 4KB ring, each lane owns its 16B slot

    const float* gsim = g_sim + c0 + 4 * lane;
    unsigned sslot = (unsigned)__cvta_generic_to_shared(&s_sim[0][4 * lane]);
    const unsigned sstride = CW * 4;   // bytes per stage

    // prologue: issue rows 0..PF-2
#pragma unroll
    for (int r = 0; r < PF - 1; ++r) {
        asm volatile("cp.async.cg.shared.global [%0], [%1], 16;\n"
                     :: "r"(sslot + r * sstride), "l"(gsim + (size_t)r * MM));
        asm volatile("cp.async.commit_group;\n");
    }

    float prev0 = 0.f, prev1 = 0.f, prev2 = 0.f, prev3 = 0.f;  // D[i-1] at this lane's 4 cols
    float prevBound = 0.f;                                      // D[i-1][c0]

    for (int i = 1; i <= NN; ++i) {
        int r = i - 1;
        int rn = r + PF - 1;
        if (rn < NN)
            asm volatile("cp.async.cg.shared.global [%0], [%1], 16;\n"
                         :: "r"(sslot + (rn & (PF - 1)) * sstride), "l"(gsim + (size_t)rn * MM));
        asm volatile("cp.async.commit_group;\n");
        asm volatile("cp.async.wait_group 7;\n");
        float4 simCur = *reinterpret_cast<const float4*>(&s_sim[r & (PF - 1)][4 * lane]);

        volatile float* pb = (volatile float*)&g_bound[(size_t)i * NB + b];
        float incoming = (b == 0) ? 0.f : *pb;   // issue early; verify later

        float cc0 = dropline - simCur.x;
        float cc1 = dropline - simCur.y;
        float cc2 = dropline - simCur.z;
        float cc3 = dropline - simCur.w;

        float edge = __shfl_up_sync(0xffffffffu, prev3, 1);   // D[i-1][c0+4*lane]
        float left0 = (lane == 0) ? prevBound : edge;

        float d0 = left0 + cc0;
        float d1 = prev0 + cc1;
        float d2 = prev1 + cc2;
        float d3 = prev2 + cc3;
        float n0 = fminf(d0, prev0);
        float n1 = fminf(d1, prev1);
        float n2 = fminf(d2, prev2);
        float n3 = fminf(d3, prev3);
        float p0 = n0;
        float p1 = fminf(p0, n1);
        float p2 = fminf(p1, n2);
        float p3 = fminf(p2, n3);

        // warp inclusive min-scan of lane totals
        float S = p3;
#pragma unroll
        for (int o = 1; o < 32; o <<= 1) {
            float v = __shfl_up_sync(0xffffffffu, S, o);
            if (lane >= o) S = fminf(S, v);
        }
        float E = __shfl_up_sync(0xffffffffu, S, 1);   // exclusive prefix (lanes > 0)

        if (b != 0) { while (incoming > 0.5f) incoming = *pb; }

        float base = (lane == 0) ? incoming : fminf(incoming, E);
        float D0 = fminf(base, p0);
        float D1 = fminf(base, p1);
        float D2 = fminf(base, p2);
        float D3 = fminf(base, p3);

        // publish right boundary ASAP (lane 31's D3 == min(incoming, S_31))
        if (lane == 31 && b < NB - 1) {
            volatile float* q = (volatile float*)&g_bound[(size_t)i * NB + (b + 1)];
            *q = D3;
        }

        bool df0 = (D0 == d0); bool uf0 = (!df0) && (D0 == prev0);
        bool df1 = (D1 == d1); bool uf1 = (!df1) && (D1 == prev1);
        bool df2 = (D2 == d2); bool uf2 = (!df2) && (D2 == prev2);
        bool df3 = (D3 == d3); bool uf3 = (!df3) && (D3 == prev3);
        unsigned db0 = __ballot_sync(0xffffffffu, df0);
        unsigned db1 = __ballot_sync(0xffffffffu, df1);
        unsigned db2 = __ballot_sync(0xffffffffu, df2);
        unsigned db3 = __ballot_sync(0xffffffffu, df3);
        unsigned ub0 = __ballot_sync(0xffffffffu, uf0);
        unsigned ub1 = __ballot_sync(0xffffffffu, uf1);
        unsigned ub2 = __ballot_sync(0xffffffffu, uf2);
        unsigned ub3 = __ballot_sync(0xffffffffu, uf3);
        if (lane < 4) {
            unsigned vd = (lane == 0) ? db0 : (lane == 1) ? db1 : (lane == 2) ? db2 : db3;
            unsigned vu = (lane == 0) ? ub0 : (lane == 1) ? ub1 : (lane == 2) ? ub2 : ub3;
            size_t rowbase = (size_t)(i - 1) * (MM / 32) + b * 4;
            g_diag[rowbase + lane] = vd;
            g_up[rowbase + lane] = vu;
        }

        prev0 = D0; prev1 = D1; prev2 = D2; prev3 = D3;
        prevBound = incoming;
    }
}

// ---------------- traceback (128-row x 256-col shared tiles) ----------------
// Decision-bit query for 0-based col jj: word (jj>>7)*4 + (jj&3), bit (jj>>2)&31.
__global__ void traceback(float* __restrict__ out) {
    __shared__ unsigned s_d[128 * 8], s_u[128 * 8];
    __shared__ int s_ij[2];
    int t = threadIdx.x;    // 256 threads
    int i = NN, j = MM;
    while (i > 0 && j > 0) {
        int ilo = (i - 127 > 1) ? (i - 127) : 1;
        int jbhi = (j - 1) >> 7;                       // block-col of current jj
        int jblo = (jbhi - 1 > 0) ? (jbhi - 1) : 0;    // stage 2 block-cols
        int rows = i - ilo + 1;
        for (int idx = t; idx < rows * 8; idx += 256) {
            int r = idx >> 3, w = idx & 7;
            size_t g = (size_t)(ilo - 1 + r) * (MM / 32) + jblo * 4 + w;
            s_d[r * 8 + w] = g_diag[g];
            s_u[r * 8 + w] = g_up[g];
        }
        __syncthreads();
        if (t == 0) {
            int jlo = jblo * 128 + 1;
            while (i >= ilo && j >= jlo) {
                int jj = j - 1;
                int r = i - ilo;
                int w = ((jj >> 7) - jblo) * 4 + (jj & 3);
                int bit = (jj >> 2) & 31;
                if ((s_d[r * 8 + w] >> bit) & 1u) {
                    out[(size_t)(i - 1) * MM + jj] = 1.0f; --i; --j;
                } else if ((s_u[r * 8 + w] >> bit) & 1u) {
                    --i;
                } else {
                    --j;
                }
            }
            s_ij[0] = i; s_ij[1] = j;
        }
        __syncthreads();
        i = s_ij[0]; j = s_ij[1];
        __syncthreads();
        // i==0 or j==0 => only zero-cost up/left moves remain, no more writes
    }
}

// ---------------- launch ----------------
extern "C" void kernel_launch(void* const* d_in, const int* in_sizes, int n_in,
                              void* d_out, int out_size) {
    (void)in_sizes; (void)n_in; (void)out_size;
    const float* text  = (const float*)d_in[2];
    const float* event = (const float*)d_in[3];
    float* out = (float*)d_out;

    init_state<<<256, 256>>>();
    fill_zero<<<4096, 256>>>(out, (size_t)NN * MM);
    normalize_rows<<<NN, 256>>>(text, 0);
    normalize_rows<<<MM, 256>>>(event, 1);
    gemm_nt<<<dim3(32, 32), 256>>>();
    for (int p = 0; p < 4; ++p) {
        int shift = 24 - 8 * p;
        hist_pass<<<2048, 256>>>(shift);
        select_pass<<<1, 256>>>(shift, p == 3 ? 1 : 0);
    }
    dp_kernel<<<NB, 32>>>();
    traceback<<<1, 256>>>(out);
}

// round 6
// speedup vs baseline: 1.0525x; 1.0071x over previous
#include <cuda_runtime.h>
#include <cstdint>
#include <cstddef>

#define NN 4096
#define MM 4096
#define DD 1024
// k = int(4096*4096*0.3) = 5033164 ; ascending 0-based rank = 16777216 - k
#define RANK_ASC 11744052u
#define NB 32          // DP column chunks
#define CW 128         // columns per chunk
#define PF 8           // sim prefetch ring depth (power of 2)
#define TBR 256        // traceback tile rows

// ---------------- static device scratch (no allocations allowed) ----------------
__device__ float    g_z[(size_t)NN * DD];
__device__ float    g_x[(size_t)MM * DD];
__device__ float    g_sim[(size_t)NN * MM];
__device__ unsigned g_diag[(size_t)NN * MM / 32];
__device__ unsigned g_up[(size_t)NN * MM / 32];
__device__ float    g_bound[(size_t)(NN + 1) * NB];
__device__ unsigned g_hist[256];
__device__ unsigned g_sel[2];   // [0]=prefix key, [1]=remaining rank
__device__ float    g_dropline;

// ---------------- helpers ----------------
__device__ __forceinline__ unsigned fkey(float f) {
    unsigned u = __float_as_uint(f);
    return (u & 0x80000000u) ? ~u : (u | 0x80000000u);
}

// ---------------- init (must reset all mutable state every replay) ----------------
__global__ void init_state() {
    int idx = blockIdx.x * blockDim.x + threadIdx.x;
    if (idx < 256) g_hist[idx] = 0u;
    if (idx == 0) { g_sel[0] = 0u; g_sel[1] = RANK_ASC; }
    int total = (NN + 1) * NB;
    for (int i = idx; i < total; i += gridDim.x * blockDim.x)
        g_bound[i] = 1.0f;   // sentinel: real D values are always <= 0
}

__global__ void fill_zero4(float4* __restrict__ out, size_t n4) {
    size_t stride = (size_t)gridDim.x * blockDim.x;
    float4 z; z.x = z.y = z.z = z.w = 0.f;
    for (size_t i = blockIdx.x * (size_t)blockDim.x + threadIdx.x; i < n4; i += stride)
        out[i] = z;
}

// ---------------- row normalize ----------------
__global__ void normalize_rows(const float* __restrict__ in, int which) {
    int row = blockIdx.x;
    int t = threadIdx.x;                 // 256 threads
    const float* p = in + (size_t)row * DD;
    float s = 0.f;
#pragma unroll
    for (int k = 0; k < 4; k++) { float v = p[t + k * 256]; s = fmaf(v, v, s); }
    __shared__ float red[256];
    red[t] = s; __syncthreads();
    for (int o = 128; o > 0; o >>= 1) { if (t < o) red[t] += red[t + o]; __syncthreads(); }
    float nrm = sqrtf(red[0]);
    float* q = (which == 0 ? g_z : g_x) + (size_t)row * DD;
#pragma unroll
    for (int k = 0; k < 4; k++) q[t + k * 256] = p[t + k * 256] / nrm;
}

// ---------------- f32 NT GEMM, double-buffered smem, f32x2 packed FMA ----------------
// Accumulation order identical to scalar version (same k sequence, per-component
// IEEE fma) => bitwise-identical sim.
__global__ void __launch_bounds__(256) gemm_nt() {
    __shared__ __align__(16) float As[2][16][132];
    __shared__ __align__(16) float Bs[2][16][132];
    int tid = threadIdx.x;
    int ty = tid >> 4;   // 0..15
    int tx = tid & 15;   // 0..15
    int bi = blockIdx.y * 128;
    int bj = blockIdx.x * 128;

    int arow0 = tid >> 2;            // 0..63
    int a4 = (tid & 3) * 4;          // 0,4,8,12

    // acc2[rp][c] packs rows (ty*8+2rp, ty*8+2rp+1) at column tx*8+c
    unsigned long long acc2[4][8];
#pragma unroll
    for (int rp = 0; rp < 4; rp++)
#pragma unroll
        for (int c = 0; c < 8; c++) acc2[rp][c] = 0ull;

    {
        float4 va0 = *reinterpret_cast<const float4*>(&g_z[(size_t)(bi + arow0) * DD + a4]);
        float4 va1 = *reinterpret_cast<const float4*>(&g_z[(size_t)(bi + arow0 + 64) * DD + a4]);
        float4 vb0 = *reinterpret_cast<const float4*>(&g_x[(size_t)(bj + arow0) * DD + a4]);
        float4 vb1 = *reinterpret_cast<const float4*>(&g_x[(size_t)(bj + arow0 + 64) * DD + a4]);
        As[0][a4 + 0][arow0] = va0.x; As[0][a4 + 1][arow0] = va0.y;
        As[0][a4 + 2][arow0] = va0.z; As[0][a4 + 3][arow0] = va0.w;
        As[0][a4 + 0][arow0 + 64] = va1.x; As[0][a4 + 1][arow0 + 64] = va1.y;
        As[0][a4 + 2][arow0 + 64] = va1.z; As[0][a4 + 3][arow0 + 64] = va1.w;
        Bs[0][a4 + 0][arow0] = vb0.x; Bs[0][a4 + 1][arow0] = vb0.y;
        Bs[0][a4 + 2][arow0] = vb0.z; Bs[0][a4 + 3][arow0] = vb0.w;
        Bs[0][a4 + 0][arow0 + 64] = vb1.x; Bs[0][a4 + 1][arow0 + 64] = vb1.y;
        Bs[0][a4 + 2][arow0 + 64] = vb1.z; Bs[0][a4 + 3][arow0 + 64] = vb1.w;
    }
    __syncthreads();

    int s = 0;
    for (int k0 = 0; k0 < DD; k0 += 16, s ^= 1) {
        float4 va0, va1, vb0, vb1;
        bool more = (k0 + 16 < DD);
        if (more) {
            int kn = k0 + 16;
            va0 = *reinterpret_cast<const float4*>(&g_z[(size_t)(bi + arow0) * DD + kn + a4]);
            va1 = *reinterpret_cast<const float4*>(&g_z[(size_t)(bi + arow0 + 64) * DD + kn + a4]);
            vb0 = *reinterpret_cast<const float4*>(&g_x[(size_t)(bj + arow0) * DD + kn + a4]);
            vb1 = *reinterpret_cast<const float4*>(&g_x[(size_t)(bj + arow0 + 64) * DD + kn + a4]);
        }
#pragma unroll
        for (int kk = 0; kk < 16; kk++) {
            const ulonglong2* ap2 = reinterpret_cast<const ulonglong2*>(&As[s][kk][ty * 8]);
            ulonglong2 aa = ap2[0], ab = ap2[1];
            unsigned long long a2[4];
            a2[0] = aa.x; a2[1] = aa.y; a2[2] = ab.x; a2[3] = ab.y;
            const float4* bp = reinterpret_cast<const float4*>(&Bs[s][kk][tx * 8]);
            float4 b0 = bp[0], b1 = bp[1];
            float bbv[8];
            bbv[0] = b0.x; bbv[1] = b0.y; bbv[2] = b0.z; bbv[3] = b0.w;
            bbv[4] = b1.x; bbv[5] = b1.y; bbv[6] = b1.z; bbv[7] = b1.w;
            unsigned long long b2[8];
#pragma unroll
            for (int c = 0; c < 8; c++)
                asm("mov.b64 %0, {%1, %1};" : "=l"(b2[c]) : "r"(__float_as_uint(bbv[c])));
#pragma unroll
            for (int rp = 0; rp < 4; rp++)
#pragma unroll
                for (int c = 0; c < 8; c++)
                    asm("fma.rn.f32x2 %0, %1, %2, %0;"
                        : "+l"(acc2[rp][c]) : "l"(a2[rp]), "l"(b2[c]));
        }
        __syncthreads();
        if (more) {
            int d = s ^ 1;
            As[d][a4 + 0][arow0] = va0.x; As[d][a4 + 1][arow0] = va0.y;
            As[d][a4 + 2][arow0] = va0.z; As[d][a4 + 3][arow0] = va0.w;
            As[d][a4 + 0][arow0 + 64] = va1.x; As[d][a4 + 1][arow0 + 64] = va1.y;
            As[d][a4 + 2][arow0 + 64] = va1.z; As[d][a4 + 3][arow0 + 64] = va1.w;
            Bs[d][a4 + 0][arow0] = vb0.x; Bs[d][a4 + 1][arow0] = vb0.y;
            Bs[d][a4 + 2][arow0] = vb0.z; Bs[d][a4 + 3][arow0] = vb0.w;
            Bs[d][a4 + 0][arow0 + 64] = vb1.x; Bs[d][a4 + 1][arow0 + 64] = vb1.y;
            Bs[d][a4 + 2][arow0 + 64] = vb1.z; Bs[d][a4 + 3][arow0 + 64] = vb1.w;
            __syncthreads();
        }
    }
#pragma unroll
    for (int rp = 0; rp < 4; rp++) {
        float lo[8], hi[8];
#pragma unroll
        for (int c = 0; c < 8; c++) {
            lo[c] = __uint_as_float((unsigned)(acc2[rp][c] & 0xffffffffull));
            hi[c] = __uint_as_float((unsigned)(acc2[rp][c] >> 32));
        }
        float* dst0 = &g_sim[(size_t)(bi + ty * 8 + 2 * rp) * MM + (bj + tx * 8)];
        float* dst1 = &g_sim[(size_t)(bi + ty * 8 + 2 * rp + 1) * MM + (bj + tx * 8)];
        float4 o;
        o.x = lo[0]; o.y = lo[1]; o.z = lo[2]; o.w = lo[3];
        *reinterpret_cast<float4*>(dst0) = o;
        o.x = lo[4]; o.y = lo[5]; o.z = lo[6]; o.w = lo[7];
        *reinterpret_cast<float4*>(dst0 + 4) = o;
        o.x = hi[0]; o.y = hi[1]; o.z = hi[2]; o.w = hi[3];
        *reinterpret_cast<float4*>(dst1) = o;
        o.x = hi[4]; o.y = hi[5]; o.z = hi[6]; o.w = hi[7];
        *reinterpret_cast<float4*>(dst1 + 4) = o;
    }
}

// ---------------- exact radix select (ascending rank RANK_ASC) ----------------
__global__ void hist_pass(int shift) {
    __shared__ unsigned sh[256];
    if (threadIdx.x < 256) sh[threadIdx.x] = 0u;
    __syncthreads();
    unsigned prefix = g_sel[0];
    int above = shift + 8;
    size_t stride = (size_t)gridDim.x * blockDim.x;
    size_t total = (size_t)NN * MM;
    for (size_t i = blockIdx.x * (size_t)blockDim.x + threadIdx.x; i < total; i += stride) {
        unsigned u = fkey(g_sim[i]);
        bool ok = (above >= 32) || ((u >> above) == (prefix >> above));
        if (ok) atomicAdd(&sh[(u >> shift) & 255u], 1u);
    }
    __syncthreads();
    if (threadIdx.x < 256 && sh[threadIdx.x]) atomicAdd(&g_hist[threadIdx.x], sh[threadIdx.x]);
}

__global__ void select_pass(int shift, int last) {
    __shared__ unsigned cnt[256];
    int t = threadIdx.x;
    cnt[t] = g_hist[t];
    g_hist[t] = 0u;   // reset for the next pass
    __syncthreads();
    if (t == 0) {
        unsigned rank = g_sel[1], cum = 0; int bin = 255;
        for (int b = 0; b < 256; b++) {
            unsigned c = cnt[b];
            if (cum + c > rank) { bin = b; break; }
            cum += c;
        }
        g_sel[0] |= ((unsigned)bin) << shift;
        g_sel[1] = rank - cum;
        if (last) {
            unsigned u = g_sel[0];
            unsigned bits = (u & 0x80000000u) ? (u & 0x7FFFFFFFu) : ~u;
            g_dropline = __uint_as_float(bits);
        }
    }
}

// ---------------- NW DP wavefront: single-warp blocks, per-row volatile handoff,
// ---------------- cp.async depth-8 sim prefetch ring ----------------
// Bit layout: 0-based sim column jj -> word (jj>>7)*4 + (jj&3), bit (jj>>2)&31.
__global__ void __launch_bounds__(32, 1) dp_kernel() {
    const int b = blockIdx.x;
    const int lane = threadIdx.x;          // 32 lanes, lane handles cols c0+4*lane .. +3
    const int c0 = b * CW;
    const float dropline = g_dropline;

    __shared__ __align__(16) float s_sim[PF][CW];   // 4KB ring, each lane owns its 16B slot

    const float* gsim = g_sim + c0 + 4 * lane;
    unsigned sslot = (unsigned)__cvta_generic_to_shared(&s_sim[0][4 * lane]);
    const unsigned sstride = CW * 4;   // bytes per stage

    // prologue: issue rows 0..PF-2
#pragma unroll
    for (int r = 0; r < PF - 1; ++r) {
        asm volatile("cp.async.cg.shared.global [%0], [%1], 16;\n"
                     :: "r"(sslot + r * sstride), "l"(gsim + (size_t)r * MM));
        asm volatile("cp.async.commit_group;\n");
    }

    float prev0 = 0.f, prev1 = 0.f, prev2 = 0.f, prev3 = 0.f;  // D[i-1] at this lane's 4 cols
    float prevBound = 0.f;                                      // D[i-1][c0]

    for (int i = 1; i <= NN; ++i) {
        int r = i - 1;
        int rn = r + PF - 1;
        if (rn < NN)
            asm volatile("cp.async.cg.shared.global [%0], [%1], 16;\n"
                         :: "r"(sslot + (rn & (PF - 1)) * sstride), "l"(gsim + (size_t)rn * MM));
        asm volatile("cp.async.commit_group;\n");
        asm volatile("cp.async.wait_group 7;\n");
        float4 simCur = *reinterpret_cast<const float4*>(&s_sim[r & (PF - 1)][4 * lane]);

        volatile float* pb = (volatile float*)&g_bound[(size_t)i * NB + b];
        float incoming = (b == 0) ? 0.f : *pb;   // issue early; verify later

        float cc0 = dropline - simCur.x;
        float cc1 = dropline - simCur.y;
        float cc2 = dropline - simCur.z;
        float cc3 = dropline - simCur.w;

        float edge = __shfl_up_sync(0xffffffffu, prev3, 1);   // D[i-1][c0+4*lane]
        float left0 = (lane == 0) ? prevBound : edge;

        float d0 = left0 + cc0;
        float d1 = prev0 + cc1;
        float d2 = prev1 + cc2;
        float d3 = prev2 + cc3;
        float n0 = fminf(d0, prev0);
        float n1 = fminf(d1, prev1);
        float n2 = fminf(d2, prev2);
        float n3 = fminf(d3, prev3);
        float p0 = n0;
        float p1 = fminf(p0, n1);
        float p2 = fminf(p1, n2);
        float p3 = fminf(p2, n3);

        // warp inclusive min-scan of lane totals
        float S = p3;
#pragma unroll
        for (int o = 1; o < 32; o <<= 1) {
            float v = __shfl_up_sync(0xffffffffu, S, o);
            if (lane >= o) S = fminf(S, v);
        }
        float E = __shfl_up_sync(0xffffffffu, S, 1);   // exclusive prefix (lanes > 0)

        if (b != 0) { while (incoming > 0.5f) incoming = *pb; }

        float base = (lane == 0) ? incoming : fminf(incoming, E);
        float D0 = fminf(base, p0);
        float D1 = fminf(base, p1);
        float D2 = fminf(base, p2);
        float D3 = fminf(base, p3);

        // publish right boundary ASAP (lane 31's D3 == min(incoming, S_31))
        if (lane == 31 && b < NB - 1) {
            volatile float* q = (volatile float*)&g_bound[(size_t)i * NB + (b + 1)];
            *q = D3;
        }

        bool df0 = (D0 == d0); bool uf0 = (!df0) && (D0 == prev0);
        bool df1 = (D1 == d1); bool uf1 = (!df1) && (D1 == prev1);
        bool df2 = (D2 == d2); bool uf2 = (!df2) && (D2 == prev2);
        bool df3 = (D3 == d3); bool uf3 = (!df3) && (D3 == prev3);
        unsigned db0 = __ballot_sync(0xffffffffu, df0);
        unsigned db1 = __ballot_sync(0xffffffffu, df1);
        unsigned db2 = __ballot_sync(0xffffffffu, df2);
        unsigned db3 = __ballot_sync(0xffffffffu, df3);
        unsigned ub0 = __ballot_sync(0xffffffffu, uf0);
        unsigned ub1 = __ballot_sync(0xffffffffu, uf1);
        unsigned ub2 = __ballot_sync(0xffffffffu, uf2);
        unsigned ub3 = __ballot_sync(0xffffffffu, uf3);
        if (lane < 4) {
            unsigned vd = (lane == 0) ? db0 : (lane == 1) ? db1 : (lane == 2) ? db2 : db3;
            unsigned vu = (lane == 0) ? ub0 : (lane == 1) ? ub1 : (lane == 2) ? ub2 : ub3;
            size_t rowbase = (size_t)(i - 1) * (MM / 32) + b * 4;
            g_diag[rowbase + lane] = vd;
            g_up[rowbase + lane] = vu;
        }

        prev0 = D0; prev1 = D1; prev2 = D2; prev3 = D3;
        prevBound = incoming;
    }
}

// ---------------- traceback: 256-row tiles, natural bit order, left-run skipping ----------------
// Stored layout per 128-col strip B: word B*4+k holds bits for jj with jj&3==k at bit jj>>2 (mod 32).
// Natural layout built at staging: word w' = local jj>>5, bit jj&31.
__device__ __forceinline__ unsigned spread4(unsigned y) {  // 8 bits -> positions 0,4,8,...,28
    y = (y | (y << 12)) & 0x000F000Fu;
    y = (y | (y << 6))  & 0x03030303u;
    y = (y | (y << 3))  & 0x11111111u;
    return y;
}
__device__ __forceinline__ unsigned natw(unsigned s0, unsigned s1, unsigned s2, unsigned s3, int w4) {
    int sh = 8 * w4;
    return spread4((s0 >> sh) & 0xFFu)
         | (spread4((s1 >> sh) & 0xFFu) << 1)
         | (spread4((s2 >> sh) & 0xFFu) << 2)
         | (spread4((s3 >> sh) & 0xFFu) << 3);
}

__global__ void traceback(float* __restrict__ out) {
    __shared__ unsigned s_d[TBR * 8], s_u[TBR * 8], s_c[TBR * 8];
    __shared__ int s_ij[2];
    int t = threadIdx.x;    // 256 threads
    int i = NN, j = MM;
    while (i > 0 && j > 0) {
        int ilo = (i - (TBR - 1) > 1) ? (i - (TBR - 1)) : 1;
        int jbhi = (j - 1) >> 7;                       // 128-col strip of current jj
        int jblo = (jbhi - 1 > 0) ? (jbhi - 1) : 0;    // stage 2 strips
        int rows = i - ilo + 1;
        for (int idx = t; idx < rows * 8; idx += 256) {
            int r = idx >> 3, wq = idx & 7;            // wq: natural word 0..7 across 2 strips
            int strip = wq >> 2, w4 = wq & 3;
            size_t gbase = (size_t)(ilo - 1 + r) * (MM / 32) + (size_t)(jblo + strip) * 4;
            unsigned d0 = g_diag[gbase + 0], d1 = g_diag[gbase + 1];
            unsigned d2 = g_diag[gbase + 2], d3 = g_diag[gbase + 3];
            unsigned u0 = g_up[gbase + 0], u1 = g_up[gbase + 1];
            unsigned u2 = g_up[gbase + 2], u3 = g_up[gbase + 3];
            unsigned nd = natw(d0, d1, d2, d3, w4);
            unsigned nu = natw(u0, u1, u2, u3, w4);
            s_d[r * 8 + wq] = nd;
            s_u[r * 8 + wq] = nu;
            s_c[r * 8 + wq] = nd | nu;
        }
        __syncthreads();
        if (t == 0) {
            int jlo = jblo * 128 + 1;                  // smallest j inside the staged strips
            while (i >= ilo && j >= jlo) {
                int jj = j - 1;
                int r = i - ilo;
                int w = (jj >> 5) - jblo * 4;          // 0..7
                int bit = jj & 31;
                unsigned dw = s_d[r * 8 + w];
                if ((dw >> bit) & 1u) {
                    out[(size_t)(i - 1) * MM + jj] = 1.0f; --i; --j;
                } else if ((s_u[r * 8 + w] >> bit) & 1u) {
                    --i;
                } else {
                    // left-run: skip to the nearest lower set bit of (diag|up)
                    unsigned m = s_c[r * 8 + w] & ((bit == 0) ? 0u : ((1u << bit) - 1u));
                    for (;;) {
                        if (m) { int nb = 31 - __clz(m); j = (jblo * 4 + w) * 32 + nb + 1; break; }
                        if (w == 0) { j = jlo - 1; break; }   // exits staged strips (or reaches j==0)
                        --w;
                        m = s_c[r * 8 + w];
                    }
                }
            }
            s_ij[0] = i; s_ij[1] = j;
        }
        __syncthreads();
        i = s_ij[0]; j = s_ij[1];
        __syncthreads();
        // i==0 or j==0 => only zero-cost up/left moves remain, no more writes
    }
}

// ---------------- launch ----------------
extern "C" void kernel_launch(void* const* d_in, const int* in_sizes, int n_in,
                              void* d_out, int out_size) {
    (void)in_sizes; (void)n_in; (void)out_size;
    const float* text  = (const float*)d_in[2];
    const float* event = (const float*)d_in[3];
    float* out = (float*)d_out;

    // Order chosen so gemm_nt is the 4th launch (ncu -s 5 -c 1 + 2 harness launches
    // captures launch #4 of ours).
    init_state<<<256, 256>>>();
    normalize_rows<<<NN, 256>>>(text, 0);
    normalize_rows<<<MM, 256>>>(event, 1);
    gemm_nt<<<dim3(32, 32), 256>>>();
    fill_zero4<<<2048, 256>>>((float4*)out, (size_t)NN * MM / 4);
    for (int p = 0; p < 4; ++p) {
        int shift = 24 - 8 * p;
        hist_pass<<<2048, 256>>>(shift);
        select_pass<<<1, 256>>>(shift, p == 3 ? 1 : 0);
    }
    dp_kernel<<<NB, 32>>>();
    traceback<<<1, 256>>>(out);
}

// round 7
// speedup vs baseline: 1.3000x; 1.2352x over previous
#include <cuda_runtime.h>
#include <cstdint>
#include <cstddef>

#define NN 4096
#define MM 4096
#define DD 1024
// k = int(4096*4096*0.3) = 5033164 ; ascending 0-based rank = 16777216 - k
#define RANK_ASC 11744052u
#define NB 32          // DP column chunks
#define CW 128         // columns per chunk
#define PF 8           // sim prefetch ring depth (power of 2)
#define TBR 256        // traceback tile rows

// ---------------- static device scratch (no allocations allowed) ----------------
__device__ float    g_z[(size_t)NN * DD];
__device__ float    g_x[(size_t)MM * DD];
__device__ float    g_sim[(size_t)NN * MM];
// decision bytes: g_dec[row*1024 + chunk*32 + lane]; bit s   = diag(col 4*lane+s)
//                                                    bit 4+s = up  (col 4*lane+s)
__device__ unsigned char g_dec[(size_t)NN * 1024];
__device__ float    g_bound[(size_t)(NN + 1) * NB];
__device__ unsigned g_hist[256];
__device__ unsigned g_sel[2];   // [0]=prefix key, [1]=remaining rank
__device__ float    g_dropline;

// ---------------- helpers ----------------
__device__ __forceinline__ unsigned fkey(float f) {
    unsigned u = __float_as_uint(f);
    return (u & 0x80000000u) ? ~u : (u | 0x80000000u);
}

// ---------------- init (must reset all mutable state every replay) ----------------
__global__ void init_state() {
    int idx = blockIdx.x * blockDim.x + threadIdx.x;
    if (idx < 256) g_hist[idx] = 0u;
    if (idx == 0) { g_sel[0] = 0u; g_sel[1] = RANK_ASC; }
    int total = (NN + 1) * NB;
    for (int i = idx; i < total; i += gridDim.x * blockDim.x)
        g_bound[i] = 1.0f;   // sentinel: real D values are always <= 0
}

__global__ void fill_zero4(float4* __restrict__ out, size_t n4) {
    size_t stride = (size_t)gridDim.x * blockDim.x;
    float4 z; z.x = z.y = z.z = z.w = 0.f;
    for (size_t i = blockIdx.x * (size_t)blockDim.x + threadIdx.x; i < n4; i += stride)
        out[i] = z;
}

// ---------------- row normalize ----------------
__global__ void normalize_rows(const float* __restrict__ in, int which) {
    int row = blockIdx.x;
    int t = threadIdx.x;                 // 256 threads
    const float* p = in + (size_t)row * DD;
    float s = 0.f;
#pragma unroll
    for (int k = 0; k < 4; k++) { float v = p[t + k * 256]; s = fmaf(v, v, s); }
    __shared__ float red[256];
    red[t] = s; __syncthreads();
    for (int o = 128; o > 0; o >>= 1) { if (t < o) red[t] += red[t + o]; __syncthreads(); }
    float nrm = sqrtf(red[0]);
    float* q = (which == 0 ? g_z : g_x) + (size_t)row * DD;
#pragma unroll
    for (int k = 0; k < 4; k++) q[t + k * 256] = p[t + k * 256] / nrm;
}

// ---------------- f32 NT GEMM, double-buffered smem, f32x2 packed FMA ----------------
// Accumulation order identical to scalar version (same k sequence, per-component
// IEEE fma) => bitwise-identical sim.
// Inner loops ordered c-outer / rp-inner so b2[c] is reused by 4 consecutive
// FFMA2s (operand-reuse cache -> rt 3 -> 2).
__global__ void __launch_bounds__(256) gemm_nt() {
    __shared__ __align__(16) float As[2][16][132];
    __shared__ __align__(16) float Bs[2][16][132];
    int tid = threadIdx.x;
    int ty = tid >> 4;   // 0..15
    int tx = tid & 15;   // 0..15
    int bi = blockIdx.y * 128;
    int bj = blockIdx.x * 128;

    int arow0 = tid >> 2;            // 0..63
    int a4 = (tid & 3) * 4;          // 0,4,8,12

    // acc2[rp][c] packs rows (ty*8+2rp, ty*8+2rp+1) at column tx*8+c
    unsigned long long acc2[4][8];
#pragma unroll
    for (int rp = 0; rp < 4; rp++)
#pragma unroll
        for (int c = 0; c < 8; c++) acc2[rp][c] = 0ull;

    {
        float4 va0 = *reinterpret_cast<const float4*>(&g_z[(size_t)(bi + arow0) * DD + a4]);
        float4 va1 = *reinterpret_cast<const float4*>(&g_z[(size_t)(bi + arow0 + 64) * DD + a4]);
        float4 vb0 = *reinterpret_cast<const float4*>(&g_x[(size_t)(bj + arow0) * DD + a4]);
        float4 vb1 = *reinterpret_cast<const float4*>(&g_x[(size_t)(bj + arow0 + 64) * DD + a4]);
        As[0][a4 + 0][arow0] = va0.x; As[0][a4 + 1][arow0] = va0.y;
        As[0][a4 + 2][arow0] = va0.z; As[0][a4 + 3][arow0] = va0.w;
        As[0][a4 + 0][arow0 + 64] = va1.x; As[0][a4 + 1][arow0 + 64] = va1.y;
        As[0][a4 + 2][arow0 + 64] = va1.z; As[0][a4 + 3][arow0 + 64] = va1.w;
        Bs[0][a4 + 0][arow0] = vb0.x; Bs[0][a4 + 1][arow0] = vb0.y;
        Bs[0][a4 + 2][arow0] = vb0.z; Bs[0][a4 + 3][arow0] = vb0.w;
        Bs[0][a4 + 0][arow0 + 64] = vb1.x; Bs[0][a4 + 1][arow0 + 64] = vb1.y;
        Bs[0][a4 + 2][arow0 + 64] = vb1.z; Bs[0][a4 + 3][arow0 + 64] = vb1.w;
    }
    __syncthreads();

    int s = 0;
    for (int k0 = 0; k0 < DD; k0 += 16, s ^= 1) {
        float4 va0, va1, vb0, vb1;
        bool more = (k0 + 16 < DD);
        if (more) {
            int kn = k0 + 16;
            va0 = *reinterpret_cast<const float4*>(&g_z[(size_t)(bi + arow0) * DD + kn + a4]);
            va1 = *reinterpret_cast<const float4*>(&g_z[(size_t)(bi + arow0 + 64) * DD + kn + a4]);
            vb0 = *reinterpret_cast<const float4*>(&g_x[(size_t)(bj + arow0) * DD + kn + a4]);
            vb1 = *reinterpret_cast<const float4*>(&g_x[(size_t)(bj + arow0 + 64) * DD + kn + a4]);
        }
#pragma unroll
        for (int kk = 0; kk < 16; kk++) {
            const ulonglong2* ap2 = reinterpret_cast<const ulonglong2*>(&As[s][kk][ty * 8]);
            ulonglong2 aa = ap2[0], ab = ap2[1];
            unsigned long long a2[4];
            a2[0] = aa.x; a2[1] = aa.y; a2[2] = ab.x; a2[3] = ab.y;
            const float4* bp = reinterpret_cast<const float4*>(&Bs[s][kk][tx * 8]);
            float4 b0 = bp[0], b1 = bp[1];
            float bbv[8];
            bbv[0] = b0.x; bbv[1] = b0.y; bbv[2] = b0.z; bbv[3] = b0.w;
            bbv[4] = b1.x; bbv[5] = b1.y; bbv[6] = b1.z; bbv[7] = b1.w;
            unsigned long long b2[8];
#pragma unroll
            for (int c = 0; c < 8; c++)
                asm("mov.b64 %0, {%1, %1};" : "=l"(b2[c]) : "r"(__float_as_uint(bbv[c])));
#pragma unroll
            for (int c = 0; c < 8; c++)
#pragma unroll
                for (int rp = 0; rp < 4; rp++)
                    asm("fma.rn.f32x2 %0, %1, %2, %0;"
                        : "+l"(acc2[rp][c]) : "l"(a2[rp]), "l"(b2[c]));
        }
        __syncthreads();
        if (more) {
            int d = s ^ 1;
            As[d][a4 + 0][arow0] = va0.x; As[d][a4 + 1][arow0] = va0.y;
            As[d][a4 + 2][arow0] = va0.z; As[d][a4 + 3][arow0] = va0.w;
            As[d][a4 + 0][arow0 + 64] = va1.x; As[d][a4 + 1][arow0 + 64] = va1.y;
            As[d][a4 + 2][arow0 + 64] = va1.z; As[d][a4 + 3][arow0 + 64] = va1.w;
            Bs[d][a4 + 0][arow0] = vb0.x; Bs[d][a4 + 1][arow0] = vb0.y;
            Bs[d][a4 + 2][arow0] = vb0.z; Bs[d][a4 + 3][arow0] = vb0.w;
            Bs[d][a4 + 0][arow0 + 64] = vb1.x; Bs[d][a4 + 1][arow0 + 64] = vb1.y;
            Bs[d][a4 + 2][arow0 + 64] = vb1.z; Bs[d][a4 + 3][arow0 + 64] = vb1.w;
            __syncthreads();
        }
    }
#pragma unroll
    for (int rp = 0; rp < 4; rp++) {
        float lo[8], hi[8];
#pragma unroll
        for (int c = 0; c < 8; c++) {
            lo[c] = __uint_as_float((unsigned)(acc2[rp][c] & 0xffffffffull));
            hi[c] = __uint_as_float((unsigned)(acc2[rp][c] >> 32));
        }
        float* dst0 = &g_sim[(size_t)(bi + ty * 8 + 2 * rp) * MM + (bj + tx * 8)];
        float* dst1 = &g_sim[(size_t)(bi + ty * 8 + 2 * rp + 1) * MM + (bj + tx * 8)];
        float4 o;
        o.x = lo[0]; o.y = lo[1]; o.z = lo[2]; o.w = lo[3];
        *reinterpret_cast<float4*>(dst0) = o;
        o.x = lo[4]; o.y = lo[5]; o.z = lo[6]; o.w = lo[7];
        *reinterpret_cast<float4*>(dst0 + 4) = o;
        o.x = hi[0]; o.y = hi[1]; o.z = hi[2]; o.w = hi[3];
        *reinterpret_cast<float4*>(dst1) = o;
        o.x = hi[4]; o.y = hi[5]; o.z = hi[6]; o.w = hi[7];
        *reinterpret_cast<float4*>(dst1 + 4) = o;
    }
}

// ---------------- exact radix select (ascending rank RANK_ASC) ----------------
// Per-warp privatized histograms cut shared-atomic conflict degree ~8x.
__global__ void hist_pass(int shift) {
    __shared__ unsigned sh[8][256];
    int t = threadIdx.x;
    int wid = t >> 5;
    for (int k = t; k < 8 * 256; k += 256) ((unsigned*)sh)[k] = 0u;
    __syncthreads();
    unsigned prefix = g_sel[0];
    int above = shift + 8;
    size_t stride = (size_t)gridDim.x * blockDim.x;
    size_t total = (size_t)NN * MM;
    for (size_t i = blockIdx.x * (size_t)blockDim.x + threadIdx.x; i < total; i += stride) {
        unsigned u = fkey(g_sim[i]);
        bool ok = (above >= 32) || ((u >> above) == (prefix >> above));
        if (ok) atomicAdd(&sh[wid][(u >> shift) & 255u], 1u);
    }
    __syncthreads();
    unsigned tot = 0;
#pragma unroll
    for (int wq = 0; wq < 8; wq++) tot += sh[wq][t];
    if (tot) atomicAdd(&g_hist[t], tot);
}

__global__ void select_pass(int shift, int last) {
    __shared__ unsigned cnt[256];
    int t = threadIdx.x;
    cnt[t] = g_hist[t];
    g_hist[t] = 0u;   // reset for the next pass
    __syncthreads();
    if (t == 0) {
        unsigned rank = g_sel[1], cum = 0; int bin = 255;
        for (int b = 0; b < 256; b++) {
            unsigned c = cnt[b];
            if (cum + c > rank) { bin = b; break; }
            cum += c;
        }
        g_sel[0] |= ((unsigned)bin) << shift;
        g_sel[1] = rank - cum;
        if (last) {
            unsigned u = g_sel[0];
            unsigned bits = (u & 0x80000000u) ? (u & 0x7FFFFFFFu) : ~u;
            g_dropline = __uint_as_float(bits);
        }
    }
}

// ---------------- NW DP wavefront: single-warp blocks, per-row volatile handoff,
// ---------------- cp.async depth-8 sim prefetch ring, per-lane byte decisions ----------------
__global__ void __launch_bounds__(32, 1) dp_kernel() {
    const int b = blockIdx.x;
    const int lane = threadIdx.x;          // 32 lanes, lane handles cols c0+4*lane .. +3
    const int c0 = b * CW;
    const float dropline = g_dropline;

    __shared__ __align__(16) float s_sim[PF][CW];   // 4KB ring, each lane owns its 16B slot

    const float* gsim = g_sim + c0 + 4 * lane;
    unsigned sslot = (unsigned)__cvta_generic_to_shared(&s_sim[0][4 * lane]);
    const unsigned sstride = CW * 4;   // bytes per stage

    // prologue: issue rows 0..PF-2
#pragma unroll
    for (int r = 0; r < PF - 1; ++r) {
        asm volatile("cp.async.cg.shared.global [%0], [%1], 16;\n"
                     :: "r"(sslot + r * sstride), "l"(gsim + (size_t)r * MM));
        asm volatile("cp.async.commit_group;\n");
    }

    float prev0 = 0.f, prev1 = 0.f, prev2 = 0.f, prev3 = 0.f;  // D[i-1] at this lane's 4 cols
    float prevBound = 0.f;                                      // D[i-1][c0]
    unsigned char* decp = g_dec + b * 32 + lane;

    for (int i = 1; i <= NN; ++i) {
        int r = i - 1;
        int rn = r + PF - 1;
        if (rn < NN)
            asm volatile("cp.async.cg.shared.global [%0], [%1], 16;\n"
                         :: "r"(sslot + (rn & (PF - 1)) * sstride), "l"(gsim + (size_t)rn * MM));
        asm volatile("cp.async.commit_group;\n");
        asm volatile("cp.async.wait_group 7;\n");
        float4 simCur = *reinterpret_cast<const float4*>(&s_sim[r & (PF - 1)][4 * lane]);

        volatile float* pb = (volatile float*)&g_bound[(size_t)i * NB + b];
        float incoming = (b == 0) ? 0.f : *pb;   // issue early; verify later

        float cc0 = dropline - simCur.x;
        float cc1 = dropline - simCur.y;
        float cc2 = dropline - simCur.z;
        float cc3 = dropline - simCur.w;

        float edge = __shfl_up_sync(0xffffffffu, prev3, 1);   // D[i-1][c0+4*lane]
        float left0 = (lane == 0) ? prevBound : edge;

        float d0 = left0 + cc0;
        float d1 = prev0 + cc1;
        float d2 = prev1 + cc2;
        float d3 = prev2 + cc3;
        float n0 = fminf(d0, prev0);
        float n1 = fminf(d1, prev1);
        float n2 = fminf(d2, prev2);
        float n3 = fminf(d3, prev3);
        float p0 = n0;
        float p1 = fminf(p0, n1);
        float p2 = fminf(p1, n2);
        float p3 = fminf(p2, n3);

        // warp inclusive min-scan of lane totals
        float S = p3;
#pragma unroll
        for (int o = 1; o < 32; o <<= 1) {
            float v = __shfl_up_sync(0xffffffffu, S, o);
            if (lane >= o) S = fminf(S, v);
        }
        float E = __shfl_up_sync(0xffffffffu, S, 1);   // exclusive prefix (lanes > 0)

        if (b != 0) { while (incoming > 0.5f) incoming = *pb; }

        float base = (lane == 0) ? incoming : fminf(incoming, E);
        float D0 = fminf(base, p0);
        float D1 = fminf(base, p1);
        float D2 = fminf(base, p2);
        float D3 = fminf(base, p3);

        // publish right boundary ASAP (lane 31's D3 == min(incoming, S_31))
        if (lane == 31 && b < NB - 1) {
            volatile float* q = (volatile float*)&g_bound[(size_t)i * NB + (b + 1)];
            *q = D3;
        }

        // pack decisions into one byte per lane (diag nibble low, up nibble high)
        bool df0 = (D0 == d0); bool uf0 = (!df0) && (D0 == prev0);
        bool df1 = (D1 == d1); bool uf1 = (!df1) && (D1 == prev1);
        bool df2 = (D2 == d2); bool uf2 = (!df2) && (D2 == prev2);
        bool df3 = (D3 == d3); bool uf3 = (!df3) && (D3 == prev3);
        unsigned byte = (df0 ? 1u : 0u) | (df1 ? 2u : 0u) | (df2 ? 4u : 0u) | (df3 ? 8u : 0u)
                      | (uf0 ? 16u : 0u) | (uf1 ? 32u : 0u) | (uf2 ? 64u : 0u) | (uf3 ? 128u : 0u);
        decp[(size_t)r * 1024] = (unsigned char)byte;

        prev0 = D0; prev1 = D1; prev2 = D2; prev3 = D3;
        prevBound = incoming;
    }
}

// ---------------- traceback: 256-row tiles, u64 nibble repack, left-run skipping ----------------
// Natural word W (cols W*32..W*32+31) of row: 8 bytes at g_dec[row*1024 + (W>>2)*32 + (W&3)*8];
// low nibbles -> diag word, high nibbles -> up word.
__device__ __forceinline__ unsigned nib_compact(unsigned long long x) {
    x &= 0x0F0F0F0F0F0F0F0Full;
    x = (x | (x >> 4))  & 0x00FF00FF00FF00FFull;
    x = (x | (x >> 8))  & 0x0000FFFF0000FFFFull;
    x = (x | (x >> 16));
    return (unsigned)x;
}

__global__ void traceback(float* __restrict__ out) {
    __shared__ uint2    s_du[TBR * 8];
    __shared__ unsigned s_c[TBR * 8];
    __shared__ int s_ij[2];
    int t = threadIdx.x;    // 256 threads
    int i = NN, j = MM;
    while (i > 0 && j > 0) {
        int ilo = (i - (TBR - 1) > 1) ? (i - (TBR - 1)) : 1;
        int jbhi = (j - 1) >> 7;                       // 128-col strip of current jj
        int jblo = (jbhi - 1 > 0) ? (jbhi - 1) : 0;    // stage 2 strips
        int rows = i - ilo + 1;
        for (int idx = t; idx < rows * 8; idx += 256) {
            int r = idx >> 3, wq = idx & 7;            // natural word 0..7 across 2 strips
            int strip = jblo + (wq >> 2), w4 = wq & 3;
            size_t boff = (size_t)(ilo - 1 + r) * 1024 + (size_t)strip * 32 + (size_t)w4 * 8;
            unsigned long long B = *reinterpret_cast<const unsigned long long*>(&g_dec[boff]);
            unsigned dw = nib_compact(B);
            unsigned uw = nib_compact(B >> 4);
            s_du[r * 8 + wq] = make_uint2(dw, uw);
            s_c[r * 8 + wq] = dw | uw;
        }
        __syncthreads();
        if (t == 0) {
            int jlo = jblo * 128 + 1;                  // smallest j inside the staged strips
            while (i >= ilo && j >= jlo) {
                int jj = j - 1;
                int r = i - ilo;
                int w = (jj >> 5) - jblo * 4;          // 0..7
                int bit = jj & 31;
                uint2 du = s_du[r * 8 + w];
                if ((du.x >> bit) & 1u) {
                    out[(size_t)(i - 1) * MM + jj] = 1.0f; --i; --j;
                } else if ((du.y >> bit) & 1u) {
                    --i;
                } else {
                    // left-run: skip to the nearest lower set bit of (diag|up)
                    unsigned m = s_c[r * 8 + w] & ((bit == 0) ? 0u : ((1u << bit) - 1u));
                    for (;;) {
                        if (m) { int nb = 31 - __clz(m); j = (jblo * 4 + w) * 32 + nb + 1; break; }
                        if (w == 0) { j = jlo - 1; break; }   // exits staged strips (or j==0)
                        --w;
                        m = s_c[r * 8 + w];
                    }
                }
            }
            s_ij[0] = i; s_ij[1] = j;
        }
        __syncthreads();
        i = s_ij[0]; j = s_ij[1];
        __syncthreads();
        // i==0 or j==0 => only zero-cost up/left moves remain, no more writes
    }
}

// ---------------- launch ----------------
extern "C" void kernel_launch(void* const* d_in, const int* in_sizes, int n_in,
                              void* d_out, int out_size) {
    (void)in_sizes; (void)n_in; (void)out_size;
    const float* text  = (const float*)d_in[2];
    const float* event = (const float*)d_in[3];
    float* out = (float*)d_out;

    // gemm_nt is the 4th launch (ncu -s 5 -c 1 + 2 harness launches -> captures it).
    init_state<<<256, 256>>>();
    normalize_rows<<<NN, 256>>>(text, 0);
    normalize_rows<<<MM, 256>>>(event, 1);
    gemm_nt<<<dim3(32, 32), 256>>>();
    fill_zero4<<<2048, 256>>>((float4*)out, (size_t)NN * MM / 4);
    for (int p = 0; p < 4; ++p) {
        int shift = 24 - 8 * p;
        hist_pass<<<2048, 256>>>(shift);
        select_pass<<<1, 256>>>(shift, p == 3 ? 1 : 0);
    }
    dp_kernel<<<NB, 32>>>();
    traceback<<<1, 256>>>(out);
}